// round 8
// baseline (speedup 1.0000x reference)
#include <cuda_runtime.h>
#include <cstdint>

#define B_ 64
#define T_ 128
#define E_ 512
#define U_ 1024
#define G_ 3072          // 3*U
#define SGST 68          // sG row stride (floats)
#define HID_OFF (B_*T_*U_)
#define NCHUNK 16        // k_rec: 1024 k rows / 64 per chunk

typedef unsigned long long ull;

// ---------------- device scratch (static, allocation-free) ----------------
__device__ __align__(256) float d_XT[T_][E_][B_];       // emb(tokens), [t_orig][e][b]
__device__ __align__(256) float d_xg[2][T_][G_][B_];    // input projections per scan step
__device__ __align__(256) float d_outs[2][T_][U_][B_];  // per-direction hidden sequences
__device__ __align__(256) float d_h[2][2][U_][B_];      // ping-pong hidden state
__device__ unsigned g_bar;                              // monotonic grid barrier

// ---------------- f32x2 helpers (Blackwell packed fp32) ----------------
__device__ __forceinline__ ull pk2(float v) {
    ull r; asm("mov.b64 %0, {%1, %1};" : "=l"(r) : "f"(v)); return r;
}
__device__ __forceinline__ ull mk2(float lo, float hi) {
    ull r; asm("mov.b64 %0, {%1, %2};" : "=l"(r) : "f"(lo), "f"(hi)); return r;
}
__device__ __forceinline__ void unpk2(ull v, float& lo, float& hi) {
    asm("mov.b64 {%0, %1}, %2;" : "=f"(lo), "=f"(hi) : "l"(v));
}
__device__ __forceinline__ void fma2(ull& d, ull a, ull b) {
    asm("fma.rn.f32x2 %0, %1, %2, %0;" : "+l"(d) : "l"(a), "l"(b));
}
__device__ __forceinline__ ull add2(ull a, ull b) {
    ull r; asm("add.rn.f32x2 %0, %1, %2;" : "=l"(r) : "l"(a), "l"(b)); return r;
}
__device__ __forceinline__ float sigf(float x) { return 1.0f / (1.0f + __expf(-x)); }

__device__ __forceinline__ void cpasync16(uint32_t saddr, const void* gaddr) {
    asm volatile("cp.async.cg.shared.global [%0], [%1], 16;" :: "r"(saddr), "l"(gaddr));
}
#define CP_COMMIT() asm volatile("cp.async.commit_group;")
#define CP_WAIT1()  asm volatile("cp.async.wait_group 1;")

union F4 { float4 v; float f[4]; ull u[2]; };

// ---------------- init: zero h state, reset barrier ----------------
__global__ void k_init() {
    int n = 2 * 2 * U_ * B_;
    float* p = &d_h[0][0][0][0];
    for (int i = blockIdx.x * blockDim.x + threadIdx.x; i < n; i += gridDim.x * blockDim.x)
        p[i] = 0.0f;
    if (blockIdx.x == 0 && threadIdx.x == 0) g_bar = 0u;
}

// ---------------- embedding gather (transposed store) ----------------
__global__ void k_embed(const int* __restrict__ tokens, const float* __restrict__ emb) {
    int t = blockIdx.x;
    int b = threadIdx.x & 63;
    int sub = threadIdx.x >> 6;
    int tok = tokens[b * T_ + t];
    const float* er = emb + (size_t)tok * E_;
    for (int e = sub; e < E_; e += 4)
        d_XT[t][e][b] = er[e];
}

// ---------------- input projection GEMM (unchanged from passing R5) ----------------
__global__ void __launch_bounds__(128) k_gemm_in(const float* __restrict__ Wf,
                                                 const float* __restrict__ Wb,
                                                 const float* __restrict__ bif,
                                                 const float* __restrict__ bib) {
    int gt = blockIdx.x, s = blockIdx.y, dir = blockIdx.z;
    int g0 = gt * 48;
    int torig = dir ? s : (T_ - 1 - s);
    const float* W  = dir ? Wb  : Wf;
    const float* bi = dir ? bib : bif;

    __shared__ __align__(16) float sW[64 * 48];
    __shared__ __align__(16) float sA[64 * 64];

    int tid = threadIdx.x;
    int kh = tid >> 6, r = tid & 63, cg = r >> 3, bg = r & 7;
    int b0 = bg << 3, c0 = cg * 6;

    ull acc[6][4];
#pragma unroll
    for (int j = 0; j < 6; j++) {
        ull init = kh ? 0ull : pk2(bi[g0 + c0 + j]);
#pragma unroll
        for (int p = 0; p < 4; p++) acc[j][p] = init;
    }

    for (int kc = 0; kc < E_ / 64; kc++) {
        __syncthreads();
        for (int idx = tid; idx < 64 * 48; idx += 128) {
            int kk = idx / 48, c = idx - kk * 48;
            sW[idx] = W[(size_t)(kc * 64 + kk) * G_ + g0 + c];
        }
        const float4* src = (const float4*)(&d_XT[torig][kc * 64][0]);
        float4* dst = (float4*)sA;
#pragma unroll
        for (int i = 0; i < 8; i++) dst[tid + i * 128] = src[tid + i * 128];
        __syncthreads();

        const float* hb  = sA + (kh * 32) * 64;
        const float* wb_ = sW + (kh * 32) * 48;
#pragma unroll 4
        for (int kk = 0; kk < 32; kk++) {
            ull hp[4];
#pragma unroll
            for (int p = 0; p < 4; p++) hp[p] = *(const ull*)(hb + kk * 64 + b0 + 2 * p);
#pragma unroll
            for (int j = 0; j < 6; j++) {
                ull us = pk2(wb_[kk * 48 + c0 + j]);
#pragma unroll
                for (int p = 0; p < 4; p++) fma2(acc[j][p], hp[p], us);
            }
        }
    }
    __syncthreads();
    ull* part = (ull*)sA;
    if (kh) {
#pragma unroll
        for (int j = 0; j < 6; j++)
#pragma unroll
            for (int p = 0; p < 4; p++) part[r * 24 + j * 4 + p] = acc[j][p];
    }
    __syncthreads();
    if (!kh) {
#pragma unroll
        for (int j = 0; j < 6; j++) {
#pragma unroll
            for (int q = 0; q < 2; q++) {
                F4 o;
                o.u[0] = add2(acc[j][2 * q + 0], part[r * 24 + j * 4 + 2 * q + 0]);
                o.u[1] = add2(acc[j][2 * q + 1], part[r * 24 + j * 4 + 2 * q + 1]);
                *(float4*)(&d_xg[dir][s][g0 + c0 + j][b0 + 4 * q]) = o.v;
            }
        }
    }
}

// ---------------- persistent recurrent kernel ----------------
// 128 CTAs (2 dirs x 64 u-chunks of 16), 256 threads, 1 CTA/SM.
// Uw slice smem-resident; h staged via double-buffered cp.async.cg (L2-coherent).
// Per-thread tile 6c x 4b with column-pair f32x2 accumulators.
// FIX vs R6: h chunk stride is 1024 float4s (4096 floats), not 256.
__global__ void __launch_bounds__(256, 1) k_rec(const float* __restrict__ Uf,
                                                const float* __restrict__ Ub,
                                                const float* __restrict__ bhf,
                                                const float* __restrict__ bhb) {
    extern __shared__ __align__(16) float smem[];
    float* sU   = smem;                // U_*48 floats = 196608 B
    float* sbuf = smem + U_ * 48;      // 2 x 4096 floats = 32768 B (staging; aliased below)

    int dir = blockIdx.x >> 6;
    int uc  = blockIdx.x & 63;
    int u0  = uc << 4;
    const float* Uw = dir ? Ub : Uf;
    const float* bh = dir ? bhb : bhf;
    int tid = threadIdx.x;
    unsigned nCTA = gridDim.x;

    // one-time: this CTA's Uw slice [1024 x 48] -> smem. col c: gate c>>4, u = u0+(c&15)
    for (int idx = tid; idx < U_ * 48; idx += 256) {
        int k = idx / 48, c = idx - k * 48;
        sU[idx] = Uw[(size_t)k * G_ + (c >> 4) * U_ + u0 + (c & 15)];
    }

    int kh = tid >> 7;                 // K split: 0 -> rows 0..31 of chunk, 1 -> 32..63
    int r  = tid & 127;
    int cg = r & 7, bg = r >> 3;
    int c0 = cg * 6, b0 = bg * 4;

    // bias as column pairs (kh0 only)
    ull binit[3];
#pragma unroll
    for (int p = 0; p < 3; p++) {
        if (kh) { binit[p] = 0ull; continue; }
        int ca = c0 + 2 * p, cb = ca + 1;
        float lo = bh[(ca >> 4) * U_ + u0 + (ca & 15)];
        float hi = bh[(cb >> 4) * U_ + u0 + (cb & 15)];
        binit[p] = mk2(lo, hi);
    }

    uint32_t sb = (uint32_t)__cvta_generic_to_shared(sbuf);

    // epilogue mapping: one (u, 4b) task per thread
    int eu = tid & 15, eb = (tid >> 4) * 4;
    int gu = u0 + eu;
    const float* xgbase = &d_xg[dir][0][0][0];

    for (int s = 0; s < T_; s++) {
        int pp = s & 1, np = pp ^ 1;
        const float4* hsrc = (const float4*)(&d_h[dir][pp][0][0]);

        // pre-issue chunks 0 and 1 (chunk = 1024 float4s = 4096 floats = 64 k-rows)
#pragma unroll
        for (int j = 0; j < 4; j++) {
            int idx = tid + j * 256;
            cpasync16(sb + idx * 16, hsrc + idx);
        }
        CP_COMMIT();
#pragma unroll
        for (int j = 0; j < 4; j++) {
            int idx = tid + j * 256;
            cpasync16(sb + 16384 + idx * 16, hsrc + 1024 + idx);
        }
        CP_COMMIT();

        ull acc[3][4];
#pragma unroll
        for (int p = 0; p < 3; p++)
#pragma unroll
            for (int b = 0; b < 4; b++) acc[p][b] = binit[p];

        for (int kc = 0; kc < NCHUNK; kc++) {
            CP_WAIT1();
            __syncthreads();           // chunk kc resident in buf[kc&1]

            const float* hb = sbuf + (kc & 1) * 4096 + (kh * 32) * 64;
            const float* ub = sU + (size_t)(kc * 64 + kh * 32) * 48;
#pragma unroll 4
            for (int kk = 0; kk < 32; kk++) {
                ull w0 = *(const ull*)(ub + kk * 48 + c0);
                ull w1 = *(const ull*)(ub + kk * 48 + c0 + 2);
                ull w2 = *(const ull*)(ub + kk * 48 + c0 + 4);
                F4 hv; hv.v = *(const float4*)(hb + kk * 64 + b0);
                ull h0 = pk2(hv.f[0]), h1 = pk2(hv.f[1]), h2 = pk2(hv.f[2]), h3 = pk2(hv.f[3]);
                fma2(acc[0][0], h0, w0); fma2(acc[0][1], h1, w0);
                fma2(acc[0][2], h2, w0); fma2(acc[0][3], h3, w0);
                fma2(acc[1][0], h0, w1); fma2(acc[1][1], h1, w1);
                fma2(acc[1][2], h2, w1); fma2(acc[1][3], h3, w1);
                fma2(acc[2][0], h0, w2); fma2(acc[2][1], h1, w2);
                fma2(acc[2][2], h2, w2); fma2(acc[2][3], h3, w2);
            }
            __syncthreads();           // all threads done reading buf[kc&1]

            if (kc + 2 < NCHUNK) {
                const float4* src = hsrc + (size_t)(kc + 2) * 1024;
                uint32_t dstb = sb + (kc & 1) * 16384;
#pragma unroll
                for (int j = 0; j < 4; j++) {
                    int idx = tid + j * 256;
                    cpasync16(dstb + idx * 16, src + idx);
                }
            }
            CP_COMMIT();
        }

        // reduce across kh: kh1 -> partials (alias buf1), kh0 combines -> sG (alias buf0)
        ull* part = (ull*)(sbuf + 4096);   // 12288 B in buf1 region
        float* sG = sbuf;                  // 48*SGST floats = 13056 B in buf0 region
        if (kh) {
#pragma unroll
            for (int p = 0; p < 3; p++)
#pragma unroll
                for (int b = 0; b < 4; b++) part[r * 12 + p * 4 + b] = acc[p][b];
        }
        __syncthreads();
        if (!kh) {
#pragma unroll
            for (int p = 0; p < 3; p++) {
#pragma unroll
                for (int b = 0; b < 4; b++) {
                    ull v = add2(acc[p][b], part[r * 12 + p * 4 + b]);
                    float lo, hi; unpk2(v, lo, hi);
                    sG[(c0 + 2 * p) * SGST + b0 + b] = lo;
                    sG[(c0 + 2 * p + 1) * SGST + b0 + b] = hi;
                }
            }
        }
        __syncthreads();

        // epilogue: gates -> h_new, one (u, 4b) per thread
        {
            const float* xs = xgbase + (size_t)s * G_ * B_;
            F4 hz, hr, hh, xz, xr, xh, hp, hn;
            hz.v = *(float4*)(sG + eu * SGST + eb);
            hr.v = *(float4*)(sG + (16 + eu) * SGST + eb);
            hh.v = *(float4*)(sG + (32 + eu) * SGST + eb);
            xz.v = *(const float4*)(xs + (size_t)gu * B_ + eb);
            xr.v = *(const float4*)(xs + (size_t)(U_ + gu) * B_ + eb);
            xh.v = *(const float4*)(xs + (size_t)(2 * U_ + gu) * B_ + eb);
            hp.v = __ldcg((const float4*)(&d_h[dir][pp][gu][eb]));
#pragma unroll
            for (int e = 0; e < 4; e++) {
                float z  = sigf(xz.f[e] + hz.f[e]);
                float rr = sigf(xr.f[e] + hr.f[e]);
                float hc = tanhf(xh.f[e] + rr * hh.f[e]);
                hn.f[e]  = z * hp.f[e] + (1.0f - z) * hc;
            }
            __stcg((float4*)(&d_h[dir][np][gu][eb]), hn.v);
            *(float4*)(&d_outs[dir][s][gu][eb]) = hn.v;
        }

        // grid barrier (monotonic; 128 co-resident CTAs)
        __syncthreads();
        if (tid == 0) {
            __threadfence();
            unsigned target = nCTA * (unsigned)(s + 1);
            unsigned v = atomicAdd(&g_bar, 1u) + 1u;
            while (v < target) {
                __nanosleep(128);
                v = atomicAdd(&g_bar, 0u);
            }
            __threadfence();
        }
        __syncthreads();
    }
}

// ---------------- combine: out[b][t][u] = outs_f[t][u][b] + outs_b[T-1-t][u][b] ----------------
__global__ void k_comb(float* __restrict__ out) {
    __shared__ float sT[32][33];
    int t = blockIdx.x, u0 = blockIdx.y * 32, b0 = blockIdx.z * 32;
    int tx = threadIdx.x, ty = threadIdx.y;
#pragma unroll
    for (int i = 0; i < 4; i++) {
        int u = ty + i * 8;
        sT[u][tx] = d_outs[0][t][u0 + u][b0 + tx] + d_outs[1][T_ - 1 - t][u0 + u][b0 + tx];
    }
    __syncthreads();
#pragma unroll
    for (int i = 0; i < 4; i++) {
        int b = ty + i * 8;
        out[((size_t)(b0 + b) * T_ + t) * U_ + u0 + tx] = sT[tx][b];
    }
}

// ---------------- hidden concat ----------------
__global__ void k_hid(float* __restrict__ out) {
    __shared__ float sT[32][33];
    int u0 = blockIdx.x * 32, dir = blockIdx.y, b0 = blockIdx.z * 32;
    int tx = threadIdx.x, ty = threadIdx.y;
#pragma unroll
    for (int i = 0; i < 4; i++) {
        int u = ty + i * 8;
        sT[u][tx] = d_outs[dir][T_ - 1][u0 + u][b0 + tx];
    }
    __syncthreads();
#pragma unroll
    for (int i = 0; i < 4; i++) {
        int b = ty + i * 8;
        out[HID_OFF + (size_t)(b0 + b) * (2 * U_) + dir * U_ + u0 + tx] = sT[tx][b];
    }
}

extern "C" void kernel_launch(void* const* d_in, const int* in_sizes, int n_in,
                              void* d_out, int out_size) {
    const int*   tokens = (const int*)d_in[0];
    const float* emb    = (const float*)d_in[1];
    const float* Wf     = (const float*)d_in[2];
    const float* Uf     = (const float*)d_in[3];
    const float* bif    = (const float*)d_in[4];
    const float* bhf    = (const float*)d_in[5];
    const float* Wb     = (const float*)d_in[6];
    const float* Ub     = (const float*)d_in[7];
    const float* bib    = (const float*)d_in[8];
    const float* bhb    = (const float*)d_in[9];
    float* out = (float*)d_out;

    const int SMEM_REC = (U_ * 48 + 8192) * (int)sizeof(float);  // 229376 B
    cudaFuncSetAttribute(k_rec, cudaFuncAttributeMaxDynamicSharedMemorySize, SMEM_REC);

    k_init<<<64, 256>>>();
    k_embed<<<T_, 256>>>(tokens, emb);
    {
        dim3 g(64, T_, 2);
        k_gemm_in<<<g, 128>>>(Wf, Wb, bif, bib);
    }
    k_rec<<<128, 256, SMEM_REC>>>(Uf, Ub, bhf, bhb);
    {
        dim3 g(T_, U_ / 32, B_ / 32);
        k_comb<<<g, dim3(32, 8)>>>(out);
    }
    {
        dim3 g(U_ / 32, 2, B_ / 32);
        k_hid<<<g, dim3(32, 8)>>>(out);
    }
    (void)in_sizes; (void)n_in; (void)out_size;
}

// round 9
// speedup vs baseline: 1.0035x; 1.0035x over previous
#include <cuda_runtime.h>
#include <cstdint>

#define B_ 64
#define T_ 128
#define E_ 512
#define U_ 1024
#define G_ 3072          // 3*U
#define SGST 68          // sG row stride (floats)
#define HID_OFF (B_*T_*U_)
#define NCHUNK 16        // k_rec: 1024 k rows / 64 per chunk

typedef unsigned long long ull;

// ---------------- device scratch (static, allocation-free) ----------------
__device__ __align__(256) float d_XT[T_][E_][B_];       // emb(tokens), [t_orig][e][b]
__device__ __align__(256) float d_xg[2][T_][G_][B_];    // input projections per scan step
__device__ __align__(256) float d_outs[2][T_][U_][B_];  // per-direction hidden sequences
__device__ __align__(256) float d_h[2][2][U_][B_];      // ping-pong hidden state
__device__ unsigned g_bar;                              // monotonic grid barrier

// ---------------- f32x2 helpers (Blackwell packed fp32) ----------------
__device__ __forceinline__ ull pk2(float v) {
    ull r; asm("mov.b64 %0, {%1, %1};" : "=l"(r) : "f"(v)); return r;
}
__device__ __forceinline__ ull mk2(float lo, float hi) {
    ull r; asm("mov.b64 %0, {%1, %2};" : "=l"(r) : "f"(lo), "f"(hi)); return r;
}
__device__ __forceinline__ void unpk2(ull v, float& lo, float& hi) {
    asm("mov.b64 {%0, %1}, %2;" : "=f"(lo), "=f"(hi) : "l"(v));
}
__device__ __forceinline__ void fma2(ull& d, ull a, ull b) {
    asm("fma.rn.f32x2 %0, %1, %2, %0;" : "+l"(d) : "l"(a), "l"(b));
}
__device__ __forceinline__ ull add2(ull a, ull b) {
    ull r; asm("add.rn.f32x2 %0, %1, %2;" : "=l"(r) : "l"(a), "l"(b)); return r;
}
__device__ __forceinline__ float sigf(float x) { return 1.0f / (1.0f + __expf(-x)); }

__device__ __forceinline__ void cpasync16(uint32_t saddr, const void* gaddr) {
    asm volatile("cp.async.cg.shared.global [%0], [%1], 16;" :: "r"(saddr), "l"(gaddr));
}
#define CP_COMMIT() asm volatile("cp.async.commit_group;")
#define CP_WAIT1()  asm volatile("cp.async.wait_group 1;")

union F4 { float4 v; float f[4]; ull u[2]; };
union F2 { float2 v; float f[2]; };

// ---------------- init: zero h state, reset barrier ----------------
__global__ void k_init() {
    int n = 2 * 2 * U_ * B_;
    float* p = &d_h[0][0][0][0];
    for (int i = blockIdx.x * blockDim.x + threadIdx.x; i < n; i += gridDim.x * blockDim.x)
        p[i] = 0.0f;
    if (blockIdx.x == 0 && threadIdx.x == 0) g_bar = 0u;
}

// ---------------- embedding gather (transposed store) ----------------
__global__ void k_embed(const int* __restrict__ tokens, const float* __restrict__ emb) {
    int t = blockIdx.x;
    int b = threadIdx.x & 63;
    int sub = threadIdx.x >> 6;
    int tok = tokens[b * T_ + t];
    const float* er = emb + (size_t)tok * E_;
    for (int e = sub; e < E_; e += 4)
        d_XT[t][e][b] = er[e];
}

// ---------------- input projection GEMM (unchanged, passing) ----------------
__global__ void __launch_bounds__(128) k_gemm_in(const float* __restrict__ Wf,
                                                 const float* __restrict__ Wb,
                                                 const float* __restrict__ bif,
                                                 const float* __restrict__ bib) {
    int gt = blockIdx.x, s = blockIdx.y, dir = blockIdx.z;
    int g0 = gt * 48;
    int torig = dir ? s : (T_ - 1 - s);
    const float* W  = dir ? Wb  : Wf;
    const float* bi = dir ? bib : bif;

    __shared__ __align__(16) float sW[64 * 48];
    __shared__ __align__(16) float sA[64 * 64];

    int tid = threadIdx.x;
    int kh = tid >> 6, r = tid & 63, cg = r >> 3, bg = r & 7;
    int b0 = bg << 3, c0 = cg * 6;

    ull acc[6][4];
#pragma unroll
    for (int j = 0; j < 6; j++) {
        ull init = kh ? 0ull : pk2(bi[g0 + c0 + j]);
#pragma unroll
        for (int p = 0; p < 4; p++) acc[j][p] = init;
    }

    for (int kc = 0; kc < E_ / 64; kc++) {
        __syncthreads();
        for (int idx = tid; idx < 64 * 48; idx += 128) {
            int kk = idx / 48, c = idx - kk * 48;
            sW[idx] = W[(size_t)(kc * 64 + kk) * G_ + g0 + c];
        }
        const float4* src = (const float4*)(&d_XT[torig][kc * 64][0]);
        float4* dst = (float4*)sA;
#pragma unroll
        for (int i = 0; i < 8; i++) dst[tid + i * 128] = src[tid + i * 128];
        __syncthreads();

        const float* hb  = sA + (kh * 32) * 64;
        const float* wb_ = sW + (kh * 32) * 48;
#pragma unroll 4
        for (int kk = 0; kk < 32; kk++) {
            ull hp[4];
#pragma unroll
            for (int p = 0; p < 4; p++) hp[p] = *(const ull*)(hb + kk * 64 + b0 + 2 * p);
#pragma unroll
            for (int j = 0; j < 6; j++) {
                ull us = pk2(wb_[kk * 48 + c0 + j]);
#pragma unroll
                for (int p = 0; p < 4; p++) fma2(acc[j][p], hp[p], us);
            }
        }
    }
    __syncthreads();
    ull* part = (ull*)sA;
    if (kh) {
#pragma unroll
        for (int j = 0; j < 6; j++)
#pragma unroll
            for (int p = 0; p < 4; p++) part[r * 24 + j * 4 + p] = acc[j][p];
    }
    __syncthreads();
    if (!kh) {
#pragma unroll
        for (int j = 0; j < 6; j++) {
#pragma unroll
            for (int q = 0; q < 2; q++) {
                F4 o;
                o.u[0] = add2(acc[j][2 * q + 0], part[r * 24 + j * 4 + 2 * q + 0]);
                o.u[1] = add2(acc[j][2 * q + 1], part[r * 24 + j * 4 + 2 * q + 1]);
                *(float4*)(&d_xg[dir][s][g0 + c0 + j][b0 + 4 * q]) = o.v;
            }
        }
    }
}

// ---------------- persistent recurrent kernel ----------------
// 128 CTAs (2 dirs x 64 u-chunks of 16), 512 threads (4 warps/SMSP), 1 CTA/SM.
// 4-way K-split; Uw slice smem-resident; h double-buffered via cp.async.cg;
// per-thread tile 6c x 4b, column-pair f32x2 accumulators.
__global__ void __launch_bounds__(512, 1) k_rec(const float* __restrict__ Uf,
                                                const float* __restrict__ Ub,
                                                const float* __restrict__ bhf,
                                                const float* __restrict__ bhb) {
    extern __shared__ __align__(16) float smem[];
    float* sU   = smem;                // U_*48 floats = 196608 B
    float* sbuf = smem + U_ * 48;      // 8192 floats = 32768 B (staging / partials / gates)

    int dir = blockIdx.x >> 6;
    int uc  = blockIdx.x & 63;
    int u0  = uc << 4;
    const float* Uw = dir ? Ub : Uf;
    const float* bh = dir ? bhb : bhf;
    int tid = threadIdx.x;
    unsigned nCTA = gridDim.x;

    // one-time: this CTA's Uw slice [1024 x 48] -> smem. col c: gate c>>4, u = u0+(c&15)
    for (int idx = tid; idx < U_ * 48; idx += 512) {
        int k = idx / 48, c = idx - k * 48;
        sU[idx] = Uw[(size_t)k * G_ + (c >> 4) * U_ + u0 + (c & 15)];
    }

    int kh = tid >> 7;                 // 0..3: K-split (16 rows per 64-row chunk each)
    int r  = tid & 127;
    int cg = r & 7, bg = r >> 3;
    int c0 = cg * 6, b0 = bg * 4;

    // bias as column pairs (kh0 only)
    ull binit[3];
#pragma unroll
    for (int p = 0; p < 3; p++) {
        if (kh) { binit[p] = 0ull; continue; }
        int ca = c0 + 2 * p, cb = ca + 1;
        float lo = bh[(ca >> 4) * U_ + u0 + (ca & 15)];
        float hi = bh[(cb >> 4) * U_ + u0 + (cb & 15)];
        binit[p] = mk2(lo, hi);
    }

    uint32_t sb = (uint32_t)__cvta_generic_to_shared(sbuf);

    // epilogue mapping: 512 tasks of (u, 2b): warp covers one u-row of 64 b (coalesced)
    int eu = tid >> 5;                 // 0..15
    int eb = (tid & 31) * 2;           // 0..62
    int gu = u0 + eu;
    const float* xgbase = &d_xg[dir][0][0][0];

    for (int s = 0; s < T_; s++) {
        int pp = s & 1, np = pp ^ 1;
        const float4* hsrc = (const float4*)(&d_h[dir][pp][0][0]);

        // prefetch epilogue operands early (consumed ~25k cyc later)
        const float* xs = xgbase + (size_t)s * G_ * B_;
        F2 xz, xr, xh, hpv;
        xz.v  = *(const float2*)(xs + (size_t)gu * B_ + eb);
        xr.v  = *(const float2*)(xs + (size_t)(U_ + gu) * B_ + eb);
        xh.v  = *(const float2*)(xs + (size_t)(2 * U_ + gu) * B_ + eb);
        hpv.v = __ldcg((const float2*)(&d_h[dir][pp][gu][eb]));

        // pre-issue chunks 0 and 1 (chunk = 1024 float4s = 64 k-rows)
#pragma unroll
        for (int j = 0; j < 2; j++) {
            int idx = tid + j * 512;
            cpasync16(sb + idx * 16, hsrc + idx);
        }
        CP_COMMIT();
#pragma unroll
        for (int j = 0; j < 2; j++) {
            int idx = tid + j * 512;
            cpasync16(sb + 16384 + idx * 16, hsrc + 1024 + idx);
        }
        CP_COMMIT();

        ull acc[3][4];
#pragma unroll
        for (int p = 0; p < 3; p++)
#pragma unroll
            for (int b = 0; b < 4; b++) acc[p][b] = binit[p];

        for (int kc = 0; kc < NCHUNK; kc++) {
            CP_WAIT1();
            __syncthreads();           // chunk kc resident in buf[kc&1]

            const float* hb = sbuf + (kc & 1) * 4096 + (kh * 16) * 64;
            const float* ub = sU + (size_t)(kc * 64 + kh * 16) * 48;
#pragma unroll 4
            for (int kk = 0; kk < 16; kk++) {
                ull w0 = *(const ull*)(ub + kk * 48 + c0);
                ull w1 = *(const ull*)(ub + kk * 48 + c0 + 2);
                ull w2 = *(const ull*)(ub + kk * 48 + c0 + 4);
                F4 hv; hv.v = *(const float4*)(hb + kk * 64 + b0);
                ull h0 = pk2(hv.f[0]), h1 = pk2(hv.f[1]), h2 = pk2(hv.f[2]), h3 = pk2(hv.f[3]);
                fma2(acc[0][0], h0, w0); fma2(acc[0][1], h1, w0);
                fma2(acc[0][2], h2, w0); fma2(acc[0][3], h3, w0);
                fma2(acc[1][0], h0, w1); fma2(acc[1][1], h1, w1);
                fma2(acc[1][2], h2, w1); fma2(acc[1][3], h3, w1);
                fma2(acc[2][0], h0, w2); fma2(acc[2][1], h1, w2);
                fma2(acc[2][2], h2, w2); fma2(acc[2][3], h3, w2);
            }
            __syncthreads();           // all threads done reading buf[kc&1]

            if (kc + 2 < NCHUNK) {
                const float4* src = hsrc + (size_t)(kc + 2) * 1024;
                uint32_t dstb = sb + (kc & 1) * 16384;
#pragma unroll
                for (int j = 0; j < 2; j++) {
                    int idx = tid + j * 512;
                    cpasync16(dstb + idx * 16, src + idx);
                }
            }
            CP_COMMIT();
        }

        // cross-kh reduce (2 rounds). part regions inside sbuf (staging done).
        ull* part = (ull*)sbuf;        // [0..1536) for kh2/kh1, [1536..3072) for kh3
        if (kh == 2) {
#pragma unroll
            for (int p = 0; p < 3; p++)
#pragma unroll
                for (int b = 0; b < 4; b++) part[r * 12 + p * 4 + b] = acc[p][b];
        }
        if (kh == 3) {
#pragma unroll
            for (int p = 0; p < 3; p++)
#pragma unroll
                for (int b = 0; b < 4; b++) part[1536 + r * 12 + p * 4 + b] = acc[p][b];
        }
        __syncthreads();
        if (kh == 0) {
#pragma unroll
            for (int p = 0; p < 3; p++)
#pragma unroll
                for (int b = 0; b < 4; b++) acc[p][b] = add2(acc[p][b], part[r * 12 + p * 4 + b]);
        }
        if (kh == 1) {
#pragma unroll
            for (int p = 0; p < 3; p++)
#pragma unroll
                for (int b = 0; b < 4; b++) acc[p][b] = add2(acc[p][b], part[1536 + r * 12 + p * 4 + b]);
        }
        __syncthreads();
        if (kh == 1) {
#pragma unroll
            for (int p = 0; p < 3; p++)
#pragma unroll
                for (int b = 0; b < 4; b++) part[r * 12 + p * 4 + b] = acc[p][b];
        }
        __syncthreads();
        float* sG = sbuf + 4096;       // 48*SGST floats (13056 B)
        if (kh == 0) {
#pragma unroll
            for (int p = 0; p < 3; p++) {
#pragma unroll
                for (int b = 0; b < 4; b++) {
                    ull v = add2(acc[p][b], part[r * 12 + p * 4 + b]);
                    float lo, hi; unpk2(v, lo, hi);
                    sG[(c0 + 2 * p) * SGST + b0 + b] = lo;
                    sG[(c0 + 2 * p + 1) * SGST + b0 + b] = hi;
                }
            }
        }
        __syncthreads();

        // epilogue: gates -> h_new, one (u, 2b) per thread (coalesced float2)
        {
            F2 hz, hr, hh, hn;
            hz.v = *(float2*)(sG + eu * SGST + eb);
            hr.v = *(float2*)(sG + (16 + eu) * SGST + eb);
            hh.v = *(float2*)(sG + (32 + eu) * SGST + eb);
#pragma unroll
            for (int e = 0; e < 2; e++) {
                float z  = sigf(xz.f[e] + hz.f[e]);
                float rr = sigf(xr.f[e] + hr.f[e]);
                float hc = tanhf(xh.f[e] + rr * hh.f[e]);
                hn.f[e]  = z * hpv.f[e] + (1.0f - z) * hc;
            }
            __stcg((float2*)(&d_h[dir][np][gu][eb]), hn.v);
            *(float2*)(&d_outs[dir][s][gu][eb]) = hn.v;
        }

        // grid barrier (monotonic; 128 co-resident CTAs)
        __syncthreads();
        if (tid == 0) {
            __threadfence();
            unsigned target = nCTA * (unsigned)(s + 1);
            unsigned v = atomicAdd(&g_bar, 1u) + 1u;
            while (v < target) {
                __nanosleep(128);
                v = atomicAdd(&g_bar, 0u);
            }
            __threadfence();
        }
        __syncthreads();
    }
}

// ---------------- combine: out[b][t][u] = outs_f[t][u][b] + outs_b[T-1-t][u][b] ----------------
__global__ void k_comb(float* __restrict__ out) {
    __shared__ float sT[32][33];
    int t = blockIdx.x, u0 = blockIdx.y * 32, b0 = blockIdx.z * 32;
    int tx = threadIdx.x, ty = threadIdx.y;
#pragma unroll
    for (int i = 0; i < 4; i++) {
        int u = ty + i * 8;
        sT[u][tx] = d_outs[0][t][u0 + u][b0 + tx] + d_outs[1][T_ - 1 - t][u0 + u][b0 + tx];
    }
    __syncthreads();
#pragma unroll
    for (int i = 0; i < 4; i++) {
        int b = ty + i * 8;
        out[((size_t)(b0 + b) * T_ + t) * U_ + u0 + tx] = sT[tx][b];
    }
}

// ---------------- hidden concat ----------------
__global__ void k_hid(float* __restrict__ out) {
    __shared__ float sT[32][33];
    int u0 = blockIdx.x * 32, dir = blockIdx.y, b0 = blockIdx.z * 32;
    int tx = threadIdx.x, ty = threadIdx.y;
#pragma unroll
    for (int i = 0; i < 4; i++) {
        int u = ty + i * 8;
        sT[u][tx] = d_outs[dir][T_ - 1][u0 + u][b0 + tx];
    }
    __syncthreads();
#pragma unroll
    for (int i = 0; i < 4; i++) {
        int b = ty + i * 8;
        out[HID_OFF + (size_t)(b0 + b) * (2 * U_) + dir * U_ + u0 + tx] = sT[tx][b];
    }
}

extern "C" void kernel_launch(void* const* d_in, const int* in_sizes, int n_in,
                              void* d_out, int out_size) {
    const int*   tokens = (const int*)d_in[0];
    const float* emb    = (const float*)d_in[1];
    const float* Wf     = (const float*)d_in[2];
    const float* Uf     = (const float*)d_in[3];
    const float* bif    = (const float*)d_in[4];
    const float* bhf    = (const float*)d_in[5];
    const float* Wb     = (const float*)d_in[6];
    const float* Ub     = (const float*)d_in[7];
    const float* bib    = (const float*)d_in[8];
    const float* bhb    = (const float*)d_in[9];
    float* out = (float*)d_out;

    const int SMEM_REC = (U_ * 48 + 8192) * (int)sizeof(float);  // 229376 B
    cudaFuncSetAttribute(k_rec, cudaFuncAttributeMaxDynamicSharedMemorySize, SMEM_REC);

    k_init<<<64, 256>>>();
    k_embed<<<T_, 256>>>(tokens, emb);
    {
        dim3 g(64, T_, 2);
        k_gemm_in<<<g, 128>>>(Wf, Wb, bif, bib);
    }
    k_rec<<<128, 512, SMEM_REC>>>(Uf, Ub, bhf, bhb);
    {
        dim3 g(T_, U_ / 32, B_ / 32);
        k_comb<<<g, dim3(32, 8)>>>(out);
    }
    {
        dim3 g(U_ / 32, 2, B_ / 32);
        k_hid<<<g, dim3(32, 8)>>>(out);
    }
    (void)in_sizes; (void)n_in; (void)out_size;
}

// round 11
// speedup vs baseline: 1.0461x; 1.0425x over previous
#include <cuda_runtime.h>
#include <cstdint>

#define B_ 64
#define T_ 128
#define E_ 512
#define U_ 1024
#define G_ 3072          // 3*U
#define SGST 68          // sG row stride (floats)
#define HID_OFF (B_*T_*U_)

typedef unsigned long long ull;

// ---------------- device scratch (static, allocation-free) ----------------
__device__ __align__(256) float d_XT[T_][E_][B_];       // emb(tokens), [t_orig][e][b]
__device__ __align__(256) float d_xg[2][T_][G_][B_];    // input projections per scan step
__device__ __align__(256) float d_outs[2][T_][U_][B_];  // per-dir hidden sequences (= h chain)
__device__ __align__(256) float d_h0[U_][B_];           // zero initial state (both dirs)
__device__ unsigned g_bar;                              // monotonic grid barrier

// ---------------- f32x2 helpers (Blackwell packed fp32) ----------------
__device__ __forceinline__ ull pk2(float v) {
    ull r; asm("mov.b64 %0, {%1, %1};" : "=l"(r) : "f"(v)); return r;
}
__device__ __forceinline__ ull mk2(float lo, float hi) {
    ull r; asm("mov.b64 %0, {%1, %2};" : "=l"(r) : "f"(lo), "f"(hi)); return r;
}
__device__ __forceinline__ void unpk2(ull v, float& lo, float& hi) {
    asm("mov.b64 {%0, %1}, %2;" : "=f"(lo), "=f"(hi) : "l"(v));
}
__device__ __forceinline__ void fma2(ull& d, ull a, ull b) {
    asm("fma.rn.f32x2 %0, %1, %2, %0;" : "+l"(d) : "l"(a), "l"(b));
}
__device__ __forceinline__ ull add2(ull a, ull b) {
    ull r; asm("add.rn.f32x2 %0, %1, %2;" : "=l"(r) : "l"(a), "l"(b)); return r;
}
__device__ __forceinline__ float sigf(float x) { return 1.0f / (1.0f + __expf(-x)); }

union F4 { float4 v; float f[4]; ull u[2]; };
union F2 { float2 v; float f[2]; };

// ---------------- init: zero h0, reset barrier ----------------
__global__ void k_init() {
    int n = U_ * B_;
    float* p = &d_h0[0][0];
    for (int i = blockIdx.x * blockDim.x + threadIdx.x; i < n; i += gridDim.x * blockDim.x)
        p[i] = 0.0f;
    if (blockIdx.x == 0 && threadIdx.x == 0) g_bar = 0u;
}

// ---------------- embedding gather (transposed store) ----------------
__global__ void k_embed(const int* __restrict__ tokens, const float* __restrict__ emb) {
    int t = blockIdx.x;
    int b = threadIdx.x & 63;
    int sub = threadIdx.x >> 6;
    int tok = tokens[b * T_ + t];
    const float* er = emb + (size_t)tok * E_;
    for (int e = sub; e < E_; e += 4)
        d_XT[t][e][b] = er[e];
}

// ---------------- input projection GEMM (unchanged, passing) ----------------
__global__ void __launch_bounds__(128) k_gemm_in(const float* __restrict__ Wf,
                                                 const float* __restrict__ Wb,
                                                 const float* __restrict__ bif,
                                                 const float* __restrict__ bib) {
    int gt = blockIdx.x, s = blockIdx.y, dir = blockIdx.z;
    int g0 = gt * 48;
    int torig = dir ? s : (T_ - 1 - s);
    const float* W  = dir ? Wb  : Wf;
    const float* bi = dir ? bib : bif;

    __shared__ __align__(16) float sW[64 * 48];
    __shared__ __align__(16) float sA[64 * 64];

    int tid = threadIdx.x;
    int kh = tid >> 6, r = tid & 63, cg = r >> 3, bg = r & 7;
    int b0 = bg << 3, c0 = cg * 6;

    ull acc[6][4];
#pragma unroll
    for (int j = 0; j < 6; j++) {
        ull init = kh ? 0ull : pk2(bi[g0 + c0 + j]);
#pragma unroll
        for (int p = 0; p < 4; p++) acc[j][p] = init;
    }

    for (int kc = 0; kc < E_ / 64; kc++) {
        __syncthreads();
        for (int idx = tid; idx < 64 * 48; idx += 128) {
            int kk = idx / 48, c = idx - kk * 48;
            sW[idx] = W[(size_t)(kc * 64 + kk) * G_ + g0 + c];
        }
        const float4* src = (const float4*)(&d_XT[torig][kc * 64][0]);
        float4* dst = (float4*)sA;
#pragma unroll
        for (int i = 0; i < 8; i++) dst[tid + i * 128] = src[tid + i * 128];
        __syncthreads();

        const float* hb  = sA + (kh * 32) * 64;
        const float* wb_ = sW + (kh * 32) * 48;
#pragma unroll 4
        for (int kk = 0; kk < 32; kk++) {
            ull hp[4];
#pragma unroll
            for (int p = 0; p < 4; p++) hp[p] = *(const ull*)(hb + kk * 64 + b0 + 2 * p);
#pragma unroll
            for (int j = 0; j < 6; j++) {
                ull us = pk2(wb_[kk * 48 + c0 + j]);
#pragma unroll
                for (int p = 0; p < 4; p++) fma2(acc[j][p], hp[p], us);
            }
        }
    }
    __syncthreads();
    ull* part = (ull*)sA;
    if (kh) {
#pragma unroll
        for (int j = 0; j < 6; j++)
#pragma unroll
            for (int p = 0; p < 4; p++) part[r * 24 + j * 4 + p] = acc[j][p];
    }
    __syncthreads();
    if (!kh) {
#pragma unroll
        for (int j = 0; j < 6; j++) {
#pragma unroll
            for (int q = 0; q < 2; q++) {
                F4 o;
                o.u[0] = add2(acc[j][2 * q + 0], part[r * 24 + j * 4 + 2 * q + 0]);
                o.u[1] = add2(acc[j][2 * q + 1], part[r * 24 + j * 4 + 2 * q + 1]);
                *(float4*)(&d_xg[dir][s][g0 + c0 + j][b0 + 4 * q]) = o.v;
            }
        }
    }
}

// ---------------- persistent recurrent kernel ----------------
// 128 CTAs (2 dirs x 64 u-chunks of 16), 512 threads, 1 CTA/SM, 4-way K-split.
// R11: h read DIRECTLY from L2 via __ldcg (no smem staging, no interior
// barriers). h chain lives in d_outs[dir][s-1] (write-once buffers; s=0 -> d_h0).
// Software-pipelined 2-row prefetch hides L2 latency; 4 warps/SMSP interleave.
__global__ void __launch_bounds__(512, 1) k_rec(const float* __restrict__ Uf,
                                                const float* __restrict__ Ub,
                                                const float* __restrict__ bhf,
                                                const float* __restrict__ bhb) {
    extern __shared__ __align__(16) float smem[];
    float* sU = smem;                // U_*48 floats = 196608 B
    float* sH = smem + U_ * 48;      // 8192 floats = 32768 B scratch (partials / gates)

    int dir = blockIdx.x >> 6;
    int uc  = blockIdx.x & 63;
    int u0  = uc << 4;
    const float* Uw = dir ? Ub : Uf;
    const float* bh = dir ? bhb : bhf;
    int tid = threadIdx.x;
    unsigned nCTA = gridDim.x;

    // one-time: this CTA's Uw slice [1024 x 48] -> smem. col c: gate c>>4, u = u0+(c&15)
    for (int idx = tid; idx < U_ * 48; idx += 512) {
        int k = idx / 48, c = idx - k * 48;
        sU[idx] = Uw[(size_t)k * G_ + (c >> 4) * U_ + u0 + (c & 15)];
    }

    int kh = tid >> 7;                 // 0..3: contiguous quarter of k = [kh*256,(kh+1)*256)
    int r  = tid & 127;
    int cg = r & 7, bg = r >> 3;
    int c0 = cg * 6, b0 = bg * 4;

    // bias as column pairs (kh0 only)
    ull binit[3];
#pragma unroll
    for (int p = 0; p < 3; p++) {
        if (kh) { binit[p] = 0ull; continue; }
        int ca = c0 + 2 * p, cb = ca + 1;
        float lo = bh[(ca >> 4) * U_ + u0 + (ca & 15)];
        float hi = bh[(cb >> 4) * U_ + u0 + (cb & 15)];
        binit[p] = mk2(lo, hi);
    }

    // epilogue mapping: 512 tasks of (u, 2b); warp covers one u-row of 64 b
    int eu = tid >> 5;                 // 0..15
    int eb = (tid & 31) * 2;           // 0..62
    int gu = u0 + eu;
    const float* xgbase = &d_xg[dir][0][0][0];
    const float* ubB = sU + (size_t)(kh * 256) * 48 + c0;

    __syncthreads();                   // sU resident

    for (int s = 0; s < T_; s++) {
        const float* hprev = (s == 0) ? &d_h0[0][0] : &d_outs[dir][s - 1][0][0];
        const float* hb = hprev + (size_t)(kh * 256) * 64 + b0;

        // prefetch epilogue operands (consumed after the ~25k-cyc mainloop)
        const float* xs = xgbase + (size_t)s * G_ * B_;
        F2 xz, xr, xh, hpv;
        xz.v  = *(const float2*)(xs + (size_t)gu * B_ + eb);
        xr.v  = *(const float2*)(xs + (size_t)(U_ + gu) * B_ + eb);
        xh.v  = *(const float2*)(xs + (size_t)(2 * U_ + gu) * B_ + eb);
        hpv.v = __ldcg((const float2*)(hprev + (size_t)gu * B_ + eb));

        ull acc[3][4];
#pragma unroll
        for (int p = 0; p < 3; p++)
#pragma unroll
            for (int b = 0; b < 4; b++) acc[p][b] = binit[p];

        // software-pipelined mainloop: 256 k rows, h via __ldcg, zero barriers
        F4 cur0, cur1;
        cur0.v = __ldcg((const float4*)(hb));
        cur1.v = __ldcg((const float4*)(hb + 64));
#pragma unroll 4
        for (int kc = 0; kc < 127; kc++) {
            F4 n0, n1;
            n0.v = __ldcg((const float4*)(hb + (2 * kc + 2) * 64));
            n1.v = __ldcg((const float4*)(hb + (2 * kc + 3) * 64));
            {
                const float* up = ubB + (2 * kc) * 48;
                ull w0 = *(const ull*)(up);
                ull w1 = *(const ull*)(up + 2);
                ull w2 = *(const ull*)(up + 4);
                ull h0 = pk2(cur0.f[0]), h1 = pk2(cur0.f[1]),
                    h2 = pk2(cur0.f[2]), h3 = pk2(cur0.f[3]);
                fma2(acc[0][0], h0, w0); fma2(acc[0][1], h1, w0);
                fma2(acc[0][2], h2, w0); fma2(acc[0][3], h3, w0);
                fma2(acc[1][0], h0, w1); fma2(acc[1][1], h1, w1);
                fma2(acc[1][2], h2, w1); fma2(acc[1][3], h3, w1);
                fma2(acc[2][0], h0, w2); fma2(acc[2][1], h1, w2);
                fma2(acc[2][2], h2, w2); fma2(acc[2][3], h3, w2);
            }
            {
                const float* up = ubB + (2 * kc + 1) * 48;
                ull w0 = *(const ull*)(up);
                ull w1 = *(const ull*)(up + 2);
                ull w2 = *(const ull*)(up + 4);
                ull h0 = pk2(cur1.f[0]), h1 = pk2(cur1.f[1]),
                    h2 = pk2(cur1.f[2]), h3 = pk2(cur1.f[3]);
                fma2(acc[0][0], h0, w0); fma2(acc[0][1], h1, w0);
                fma2(acc[0][2], h2, w0); fma2(acc[0][3], h3, w0);
                fma2(acc[1][0], h0, w1); fma2(acc[1][1], h1, w1);
                fma2(acc[1][2], h2, w1); fma2(acc[1][3], h3, w1);
                fma2(acc[2][0], h0, w2); fma2(acc[2][1], h1, w2);
                fma2(acc[2][2], h2, w2); fma2(acc[2][3], h3, w2);
            }
            cur0 = n0; cur1 = n1;
        }
        // tail: rows 254, 255
#pragma unroll
        for (int t2 = 0; t2 < 2; t2++) {
            const float* up = ubB + (254 + t2) * 48;
            ull w0 = *(const ull*)(up);
            ull w1 = *(const ull*)(up + 2);
            ull w2 = *(const ull*)(up + 4);
            F4& cv = t2 ? cur1 : cur0;
            ull h0 = pk2(cv.f[0]), h1 = pk2(cv.f[1]), h2 = pk2(cv.f[2]), h3 = pk2(cv.f[3]);
            fma2(acc[0][0], h0, w0); fma2(acc[0][1], h1, w0);
            fma2(acc[0][2], h2, w0); fma2(acc[0][3], h3, w0);
            fma2(acc[1][0], h0, w1); fma2(acc[1][1], h1, w1);
            fma2(acc[1][2], h2, w1); fma2(acc[1][3], h3, w1);
            fma2(acc[2][0], h0, w2); fma2(acc[2][1], h1, w2);
            fma2(acc[2][2], h2, w2); fma2(acc[2][3], h3, w2);
        }

        // cross-kh reduce. P0 = ull[0,1536); P1 = ull[1536,3072).
        // (sH free: previous step's sG reads are ordered by the grid-barrier syncs)
        ull* part = (ull*)sH;
        if (kh == 2) {
#pragma unroll
            for (int p = 0; p < 3; p++)
#pragma unroll
                for (int b = 0; b < 4; b++) part[r * 12 + p * 4 + b] = acc[p][b];
        }
        if (kh == 3) {
#pragma unroll
            for (int p = 0; p < 3; p++)
#pragma unroll
                for (int b = 0; b < 4; b++) part[1536 + r * 12 + p * 4 + b] = acc[p][b];
        }
        __syncthreads();
        if (kh == 0) {
#pragma unroll
            for (int p = 0; p < 3; p++)
#pragma unroll
                for (int b = 0; b < 4; b++) acc[p][b] = add2(acc[p][b], part[r * 12 + p * 4 + b]);
        }
        if (kh == 1) {
#pragma unroll
            for (int p = 0; p < 3; p++)
#pragma unroll
                for (int b = 0; b < 4; b++) acc[p][b] = add2(acc[p][b], part[1536 + r * 12 + p * 4 + b]);
        }
        __syncthreads();
        if (kh == 1) {
#pragma unroll
            for (int p = 0; p < 3; p++)
#pragma unroll
                for (int b = 0; b < 4; b++) part[r * 12 + p * 4 + b] = acc[p][b];
        }
        __syncthreads();
        float* sG = sH + 3072;         // floats [3072, 6336) — P1 consumed by now
        if (kh == 0) {
#pragma unroll
            for (int p = 0; p < 3; p++) {
#pragma unroll
                for (int b = 0; b < 4; b++) {
                    ull v = add2(acc[p][b], part[r * 12 + p * 4 + b]);
                    float lo, hi; unpk2(v, lo, hi);
                    sG[(c0 + 2 * p) * SGST + b0 + b] = lo;
                    sG[(c0 + 2 * p + 1) * SGST + b0 + b] = hi;
                }
            }
        }
        __syncthreads();

        // epilogue: gates -> h_new, one (u, 2b) per thread; single store to d_outs[s]
        {
            F2 hz, hr, hh, hn;
            hz.v = *(float2*)(sG + eu * SGST + eb);
            hr.v = *(float2*)(sG + (16 + eu) * SGST + eb);
            hh.v = *(float2*)(sG + (32 + eu) * SGST + eb);
#pragma unroll
            for (int e = 0; e < 2; e++) {
                float z  = sigf(xz.f[e] + hz.f[e]);
                float rr = sigf(xr.f[e] + hr.f[e]);
                float hc = tanhf(xh.f[e] + rr * hh.f[e]);
                hn.f[e]  = z * hpv.f[e] + (1.0f - z) * hc;
            }
            __stcg((float2*)(&d_outs[dir][s][gu][eb]), hn.v);
        }

        // grid barrier (monotonic; 128 co-resident CTAs)
        __syncthreads();
        if (tid == 0) {
            __threadfence();
            unsigned target = nCTA * (unsigned)(s + 1);
            unsigned v = atomicAdd(&g_bar, 1u) + 1u;
            while (v < target) {
                __nanosleep(128);
                v = atomicAdd(&g_bar, 0u);
            }
            __threadfence();
        }
        __syncthreads();
    }
}

// ---------------- combine: out[b][t][u] = outs_f[t][u][b] + outs_b[T-1-t][u][b] ----------------
__global__ void k_comb(float* __restrict__ out) {
    __shared__ float sT[32][33];
    int t = blockIdx.x, u0 = blockIdx.y * 32, b0 = blockIdx.z * 32;
    int tx = threadIdx.x, ty = threadIdx.y;
#pragma unroll
    for (int i = 0; i < 4; i++) {
        int u = ty + i * 8;
        sT[u][tx] = d_outs[0][t][u0 + u][b0 + tx] + d_outs[1][T_ - 1 - t][u0 + u][b0 + tx];
    }
    __syncthreads();
#pragma unroll
    for (int i = 0; i < 4; i++) {
        int b = ty + i * 8;
        out[((size_t)(b0 + b) * T_ + t) * U_ + u0 + tx] = sT[tx][b];
    }
}

// ---------------- hidden concat ----------------
__global__ void k_hid(float* __restrict__ out) {
    __shared__ float sT[32][33];
    int u0 = blockIdx.x * 32, dir = blockIdx.y, b0 = blockIdx.z * 32;
    int tx = threadIdx.x, ty = threadIdx.y;
#pragma unroll
    for (int i = 0; i < 4; i++) {
        int u = ty + i * 8;
        sT[u][tx] = d_outs[dir][T_ - 1][u0 + u][b0 + tx];
    }
    __syncthreads();
#pragma unroll
    for (int i = 0; i < 4; i++) {
        int b = ty + i * 8;
        out[HID_OFF + (size_t)(b0 + b) * (2 * U_) + dir * U_ + u0 + tx] = sT[tx][b];
    }
}

extern "C" void kernel_launch(void* const* d_in, const int* in_sizes, int n_in,
                              void* d_out, int out_size) {
    const int*   tokens = (const int*)d_in[0];
    const float* emb    = (const float*)d_in[1];
    const float* Wf     = (const float*)d_in[2];
    const float* Uf     = (const float*)d_in[3];
    const float* bif    = (const float*)d_in[4];
    const float* bhf    = (const float*)d_in[5];
    const float* Wb     = (const float*)d_in[6];
    const float* Ub     = (const float*)d_in[7];
    const float* bib    = (const float*)d_in[8];
    const float* bhb    = (const float*)d_in[9];
    float* out = (float*)d_out;

    const int SMEM_REC = (U_ * 48 + 8192) * (int)sizeof(float);  // 229376 B
    cudaFuncSetAttribute(k_rec, cudaFuncAttributeMaxDynamicSharedMemorySize, SMEM_REC);

    k_init<<<64, 256>>>();
    k_embed<<<T_, 256>>>(tokens, emb);
    {
        dim3 g(64, T_, 2);
        k_gemm_in<<<g, 128>>>(Wf, Wb, bif, bib);
    }
    k_rec<<<128, 512, SMEM_REC>>>(Uf, Ub, bhf, bhb);
    {
        dim3 g(T_, U_ / 32, B_ / 32);
        k_comb<<<g, dim3(32, 8)>>>(out);
    }
    {
        dim3 g(U_ / 32, 2, B_ / 32);
        k_hid<<<g, dim3(32, 8)>>>(out);
    }
    (void)in_sizes; (void)n_in; (void)out_size;
}